// round 7
// baseline (speedup 1.0000x reference)
#include <cuda_runtime.h>
#include <cstdint>
#include <cstddef>

// Problem constants
#define BATCH  4
#define NSEQ   2048
#define DMODEL 1024
#define NHEAD  16
#define DKH    64
#define MROWS  (BATCH * NSEQ)   // 8192
#define NEGVAL (-1e11f)

// ---------------- scratch (device globals; no allocation allowed) ----------
__device__ float    g_Q[BATCH * NHEAD * NSEQ * DKH];   // (B,H,N,DK)
__device__ float    g_K[BATCH * NHEAD * NSEQ * DKH];
__device__ float    g_V[BATCH * NHEAD * NSEQ * DKH];
__device__ float    g_C[BATCH * NSEQ * DMODEL];        // attention context (B,N,D)
__device__ unsigned g_pmask[BATCH * NSEQ * NSEQ / 32]; // bit-packed mask

// ---------------- helpers ---------------------------------------------------
__device__ __forceinline__ uint32_t f2tf32(float x) {
    uint32_t r;
    asm("cvt.rna.tf32.f32 %0, %1;" : "=r"(r) : "f"(x));
    return r;
}

__device__ __forceinline__ void mma_tf32(float* c, const uint32_t* a,
                                         uint32_t b0, uint32_t b1) {
    asm volatile(
        "mma.sync.aligned.m16n8k8.row.col.f32.tf32.tf32.f32 "
        "{%0,%1,%2,%3}, {%4,%5,%6,%7}, {%8,%9}, {%0,%1,%2,%3};"
        : "+f"(c[0]), "+f"(c[1]), "+f"(c[2]), "+f"(c[3])
        : "r"(a[0]), "r"(a[1]), "r"(a[2]), "r"(a[3]), "r"(b0), "r"(b1));
}

// ---------------- mask bit-pack: 67MB int32 -> 2MB bits --------------------
__global__ void pack_mask_kernel(const int* __restrict__ mask) {
    int idx = blockIdx.x * blockDim.x + threadIdx.x;
    unsigned bit = (mask[idx] != 0) ? 1u : 0u;
    unsigned w = __ballot_sync(0xffffffffu, bit);
    if ((threadIdx.x & 31) == 0) g_pmask[idx >> 5] = w;
}

// ---------------- projection GEMM: 3xTF32 mma.sync --------------------------
// C(8192x1024) = A @ W + bias.  Block tile 128x128, BK=16, 256 threads (8 warps,
// 2x4 warp grid, warp tile 64x32).  Split-precision: err ~ fp32.
template <bool SPLIT>
__global__ __launch_bounds__(256)
void proj_mma_kernel(const float* __restrict__ A, const float* __restrict__ W,
                     const float* __restrict__ bias, float* __restrict__ out) {
    __shared__ uint32_t AsH[16][136];   // [k][m] tf32-hi
    __shared__ uint32_t AsL[16][136];   // [k][m] tf32-lo
    __shared__ uint32_t BsH[16][136];   // [k][n]
    __shared__ uint32_t BsL[16][136];

    const int tid = threadIdx.x;
    const int w = tid >> 5, l = tid & 31;
    const int lg = l >> 2, lk = l & 3;
    const int wm = (w >> 2) * 64;       // 0,64
    const int wn = (w & 3) * 32;        // 0,32,64,96
    const int m0 = blockIdx.y * 128, n0 = blockIdx.x * 128;

    float c[4][4][4];
#pragma unroll
    for (int mi = 0; mi < 4; ++mi)
#pragma unroll
        for (int nj = 0; nj < 4; ++nj)
#pragma unroll
            for (int t = 0; t < 4; ++t) c[mi][nj][t] = 0.f;

    for (int kt = 0; kt < DMODEL; kt += 16) {
        // prefetch to registers
        float4 av[2], bv[2];
#pragma unroll
        for (int i = 0; i < 2; ++i) {
            int v = tid + 256 * i;
            int am = v & 127, ak4 = (v >> 7) * 4;            // A: row am, k ak4..+3
            av[i] = *(const float4*)(A + (size_t)(m0 + am) * DMODEL + kt + ak4);
            int bk = v >> 5, bn4 = (v & 31) * 4;             // B: row bk, n bn4..+3
            bv[i] = *(const float4*)(W + (size_t)(kt + bk) * DMODEL + n0 + bn4);
        }
        __syncthreads();   // previous tile fully consumed
#pragma unroll
        for (int i = 0; i < 2; ++i) {
            int v = tid + 256 * i;
            int am = v & 127, ak4 = (v >> 7) * 4;
            const float* af = (const float*)&av[i];
#pragma unroll
            for (int j = 0; j < 4; ++j) {
                uint32_t hi = f2tf32(af[j]);
                AsH[ak4 + j][am] = hi;
                AsL[ak4 + j][am] = f2tf32(af[j] - __uint_as_float(hi));
            }
            int bk = v >> 5, bn4 = (v & 31) * 4;
            const float* bf = (const float*)&bv[i];
#pragma unroll
            for (int j = 0; j < 4; ++j) {
                uint32_t hi = f2tf32(bf[j]);
                BsH[bk][bn4 + j] = hi;
                BsL[bk][bn4 + j] = f2tf32(bf[j] - __uint_as_float(hi));
            }
        }
        __syncthreads();

#pragma unroll
        for (int ks = 0; ks < 16; ks += 8) {
            uint32_t aH[4][4], aL[4][4];
#pragma unroll
            for (int mi = 0; mi < 4; ++mi) {
                int mbase = wm + 16 * mi + lg;
                aH[mi][0] = AsH[ks + lk][mbase];
                aH[mi][1] = AsH[ks + lk][mbase + 8];
                aH[mi][2] = AsH[ks + lk + 4][mbase];
                aH[mi][3] = AsH[ks + lk + 4][mbase + 8];
                aL[mi][0] = AsL[ks + lk][mbase];
                aL[mi][1] = AsL[ks + lk][mbase + 8];
                aL[mi][2] = AsL[ks + lk + 4][mbase];
                aL[mi][3] = AsL[ks + lk + 4][mbase + 8];
            }
#pragma unroll
            for (int nj = 0; nj < 4; ++nj) {
                int nb = wn + 8 * nj + lg;
                uint32_t bH0 = BsH[ks + lk][nb], bH1 = BsH[ks + lk + 4][nb];
                uint32_t bL0 = BsL[ks + lk][nb], bL1 = BsL[ks + lk + 4][nb];
#pragma unroll
                for (int mi = 0; mi < 4; ++mi) {
                    mma_tf32(c[mi][nj], aH[mi], bH0, bH1);
                    mma_tf32(c[mi][nj], aH[mi], bL0, bL1);
                    mma_tf32(c[mi][nj], aL[mi], bH0, bH1);
                }
            }
        }
    }

    // epilogue: bias + store (optionally remapped to (B,H,N,DK))
#pragma unroll
    for (int mi = 0; mi < 4; ++mi) {
#pragma unroll
        for (int nj = 0; nj < 4; ++nj) {
            int col = n0 + wn + 8 * nj + 2 * lk;
            float b0 = __ldg(&bias[col]), b1 = __ldg(&bias[col + 1]);
#pragma unroll
            for (int half = 0; half < 2; ++half) {
                int m = m0 + wm + 16 * mi + lg + 8 * half;
                float2 v;
                v.x = c[mi][nj][2 * half + 0] + b0;
                v.y = c[mi][nj][2 * half + 1] + b1;
                size_t idx;
                if (SPLIT) {
                    int b = m >> 11, row = m & 2047;
                    int h = col >> 6, dk = col & 63;
                    idx = (((size_t)(b * NHEAD + h) * NSEQ + row) * DKH + dk);
                } else {
                    idx = (size_t)m * DMODEL + col;
                }
                *(float2*)&out[idx] = v;
            }
        }
    }
}

// ---------------- fused masked flash attention (tf32 mma) -------------------
// grid: (N/64, B*H), block 256 (8 warps).  64-query tile, 64-key tiles.
// S = Q@K^T via mma -> smem; proven scalar softmax on smem; PV via mma.
// R5: K/V global loads software-pipelined (prefetch kt+1 into registers during
//     compute of kt); Ps aliases Qs (dead after qf preload) -> 54.5KB smem.
#define QPAD 68
#define KPAD 72
__global__ __launch_bounds__(256)
void attn_kernel() {
    extern __shared__ char smraw[];
    uint32_t* Qs = (uint32_t*)smraw;                    // [64][QPAD] (q-major, tf32)
    float*    Ps = (float*)smraw;                       // aliases Qs (dead after preload)
    uint32_t* Ks = (uint32_t*)(smraw + 64 * QPAD * 4);  // [64][KPAD] ([d][key], tf32)
    uint32_t* Vs = (uint32_t*)(smraw + 64 * QPAD * 4 + 64 * KPAD * 4); // [key][KPAD]
    float*    Cr = (float*)(smraw + 64 * QPAD * 4 + 2 * 64 * KPAD * 4); // [64]

    const int tid = threadIdx.x;
    const int w = tid >> 5, l = tid & 31;
    const int lg = l >> 2, lk = l & 3;
    const int rb = (w >> 1) * 16;       // warp row band
    const int cb = (w & 1) * 32;        // warp col half
    const int tx = tid & 15, ty = tid >> 4;
    const int bh = blockIdx.y;
    const int b = bh >> 4;
    const int h = bh & 15;
    const int q0 = blockIdx.x * 64;

    const float* Qg = g_Q + ((size_t)bh * NSEQ + q0) * DKH;
    const float* Kg = g_K + (size_t)bh * NSEQ * DKH;
    const float* Vg = g_V + (size_t)bh * NSEQ * DKH;

    // ---- load Q tile (rounded to tf32), q-major ----
#pragma unroll
    for (int i = 0; i < 4; ++i) {
        int v = tid + 256 * i;
        int row = v >> 4, d4 = (v & 15) * 4;
        float4 q = *(const float4*)(Qg + (size_t)row * DKH + d4);
        Qs[row * QPAD + d4 + 0] = f2tf32(q.x);
        Qs[row * QPAD + d4 + 1] = f2tf32(q.y);
        Qs[row * QPAD + d4 + 2] = f2tf32(q.z);
        Qs[row * QPAD + d4 + 3] = f2tf32(q.w);
    }
    __syncthreads();

    // preload Q fragments (rows rb..rb+15, all 8 k-steps); Qs dead afterwards
    uint32_t qf[8][4];
#pragma unroll
    for (int ks = 0; ks < 8; ++ks) {
        qf[ks][0] = Qs[(rb + lg) * QPAD + ks * 8 + lk];
        qf[ks][1] = Qs[(rb + lg + 8) * QPAD + ks * 8 + lk];
        qf[ks][2] = Qs[(rb + lg) * QPAD + ks * 8 + lk + 4];
        qf[ks][3] = Qs[(rb + lg + 8) * QPAD + ks * 8 + lk + 4];
    }

    // softmax state (owned by the (tx,ty) view threads)
    float m_run[4], l_run[4];
#pragma unroll
    for (int i = 0; i < 4; ++i) { m_run[i] = -1e30f; l_run[i] = 0.f; }

    // PV accumulators (owned by the mma view threads)
    float o[4][4];
#pragma unroll
    for (int nj = 0; nj < 4; ++nj)
#pragma unroll
        for (int t = 0; t < 4; ++t) o[nj][t] = 0.f;

    const int maskRowBase = b * NSEQ + q0;

    // ---- register prefetch of K/V tile 0 ----
    float4 kreg[4], vreg[4];
#pragma unroll
    for (int i = 0; i < 4; ++i) {
        int v = tid + 256 * i;
        int kkey = v & 63, kd4 = (v >> 6) * 4;
        kreg[i] = *(const float4*)(Kg + (size_t)kkey * DKH + kd4);
        int vkey = v >> 4, vd4 = (v & 15) * 4;
        vreg[i] = *(const float4*)(Vg + (size_t)vkey * DKH + vd4);
    }

    for (int kt = 0; kt < NSEQ / 64; ++kt) {
        __syncthreads();   // prior iteration done with Ks/Vs/Ps
        // ---- store prefetched K (transposed [d][key]) and V ([key][dk]) ----
#pragma unroll
        for (int i = 0; i < 4; ++i) {
            int v = tid + 256 * i;
            int kkey = v & 63, kd4 = (v >> 6) * 4;
            Ks[(kd4 + 0) * KPAD + kkey] = f2tf32(kreg[i].x);
            Ks[(kd4 + 1) * KPAD + kkey] = f2tf32(kreg[i].y);
            Ks[(kd4 + 2) * KPAD + kkey] = f2tf32(kreg[i].z);
            Ks[(kd4 + 3) * KPAD + kkey] = f2tf32(kreg[i].w);
            int vkey = v >> 4, vd4 = (v & 15) * 4;
            Vs[vkey * KPAD + vd4 + 0] = f2tf32(vreg[i].x);
            Vs[vkey * KPAD + vd4 + 1] = f2tf32(vreg[i].y);
            Vs[vkey * KPAD + vd4 + 2] = f2tf32(vreg[i].z);
            Vs[vkey * KPAD + vd4 + 3] = f2tf32(vreg[i].w);
        }
        __syncthreads();

        // ---- issue global loads for tile kt+1 (latency hidden by compute) ----
        if (kt + 1 < NSEQ / 64) {
#pragma unroll
            for (int i = 0; i < 4; ++i) {
                int v = tid + 256 * i;
                int kkey = v & 63, kd4 = (v >> 6) * 4;
                kreg[i] = *(const float4*)(Kg + (size_t)((kt + 1) * 64 + kkey) * DKH + kd4);
                int vkey = v >> 4, vd4 = (v & 15) * 4;
                vreg[i] = *(const float4*)(Vg + (size_t)((kt + 1) * 64 + vkey) * DKH + vd4);
            }
        }

        // ---- S = Q @ K^T (mma), store to Ps ----
        {
            float sc[4][4];
#pragma unroll
            for (int nj = 0; nj < 4; ++nj)
#pragma unroll
                for (int t = 0; t < 4; ++t) sc[nj][t] = 0.f;
#pragma unroll
            for (int ks = 0; ks < 8; ++ks) {
#pragma unroll
                for (int nj = 0; nj < 4; ++nj) {
                    int nb = cb + 8 * nj + lg;
                    uint32_t b0 = Ks[(ks * 8 + lk) * KPAD + nb];
                    uint32_t b1 = Ks[(ks * 8 + lk + 4) * KPAD + nb];
                    mma_tf32(sc[nj], qf[ks], b0, b1);
                }
            }
#pragma unroll
            for (int nj = 0; nj < 4; ++nj) {
                int col = cb + 8 * nj + 2 * lk;
                *(float2*)&Ps[(rb + lg) * QPAD + col] = make_float2(sc[nj][0], sc[nj][1]);
                *(float2*)&Ps[(rb + lg + 8) * QPAD + col] = make_float2(sc[nj][2], sc[nj][3]);
            }
        }
        __syncthreads();

        // ---- scalar masked online softmax on Ps ----
        {
            int wcol = kt * 2 + (tx >> 3);
            int bit0 = (4 * tx) & 31;
#pragma unroll
            for (int i = 0; i < 4; ++i) {
                int row = 4 * ty + i;
                float4 sv = *(const float4*)&Ps[row * QPAD + 4 * tx];
                float s[4] = {sv.x, sv.y, sv.z, sv.w};
                unsigned mw = g_pmask[(size_t)(maskRowBase + row) * (NSEQ / 32) + wcol];
                float rm = -1e30f;
#pragma unroll
                for (int j = 0; j < 4; ++j) {
                    float vv = ((mw >> (bit0 + j)) & 1u) ? s[j] * 0.125f : NEGVAL;
                    s[j] = vv;
                    rm = fmaxf(rm, vv);
                }
#pragma unroll
                for (int off = 8; off; off >>= 1)
                    rm = fmaxf(rm, __shfl_xor_sync(0xffffffffu, rm, off));
                float mn = fmaxf(m_run[i], rm);
                float corr = __expf(m_run[i] - mn);
                m_run[i] = mn;
                float p[4], ls = 0.f;
#pragma unroll
                for (int j = 0; j < 4; ++j) {
                    p[j] = __uint_as_float(f2tf32(__expf(s[j] - mn)));
                    ls += p[j];
                }
#pragma unroll
                for (int off = 8; off; off >>= 1)
                    ls += __shfl_xor_sync(0xffffffffu, ls, off);
                l_run[i] = l_run[i] * corr + ls;
                *(float4*)&Ps[row * QPAD + 4 * tx] = make_float4(p[0], p[1], p[2], p[3]);
                if (tx == 0) Cr[row] = corr;
            }
        }
        __syncthreads();

        // ---- O = O*corr + P @ V (mma) ----
        {
            float cr0 = Cr[rb + lg], cr1 = Cr[rb + lg + 8];
#pragma unroll
            for (int nj = 0; nj < 4; ++nj) {
                o[nj][0] *= cr0; o[nj][1] *= cr0;
                o[nj][2] *= cr1; o[nj][3] *= cr1;
            }
#pragma unroll
            for (int ks = 0; ks < 8; ++ks) {
                uint32_t af[4];
                af[0] = __float_as_uint(Ps[(rb + lg) * QPAD + ks * 8 + lk]);
                af[1] = __float_as_uint(Ps[(rb + lg + 8) * QPAD + ks * 8 + lk]);
                af[2] = __float_as_uint(Ps[(rb + lg) * QPAD + ks * 8 + lk + 4]);
                af[3] = __float_as_uint(Ps[(rb + lg + 8) * QPAD + ks * 8 + lk + 4]);
#pragma unroll
                for (int nj = 0; nj < 4; ++nj) {
                    int nb = cb + 8 * nj + lg;
                    uint32_t b0 = Vs[(ks * 8 + lk) * KPAD + nb];
                    uint32_t b1 = Vs[(ks * 8 + lk + 4) * KPAD + nb];
                    mma_tf32(o[nj], af, b0, b1);
                }
            }
        }
    }

    // ---- normalize and write context ----
    __syncthreads();
#pragma unroll
    for (int i = 0; i < 4; ++i)
        if (tx == 0) Cr[4 * ty + i] = 1.0f / l_run[i];
    __syncthreads();

    float inv0 = Cr[rb + lg], inv1 = Cr[rb + lg + 8];
    float* Cg = g_C + ((size_t)(b * NSEQ + q0)) * DMODEL + h * DKH;
#pragma unroll
    for (int nj = 0; nj < 4; ++nj) {
        int col = cb + 8 * nj + 2 * lk;
        *(float2*)&Cg[(size_t)(rb + lg) * DMODEL + col] =
            make_float2(o[nj][0] * inv0, o[nj][1] * inv0);
        *(float2*)&Cg[(size_t)(rb + lg + 8) * DMODEL + col] =
            make_float2(o[nj][2] * inv1, o[nj][3] * inv1);
    }
}

// ---------------- launch ----------------------------------------------------
extern "C" void kernel_launch(void* const* d_in, const int* in_sizes, int n_in,
                              void* d_out, int out_size) {
    const float* query = (const float*)d_in[0];
    const float* key   = (const float*)d_in[1];
    const float* value = (const float*)d_in[2];
    const int*   mask  = (const int*)d_in[3];
    const float* Wq = (const float*)d_in[4];
    const float* bq = (const float*)d_in[5];
    const float* Wk = (const float*)d_in[6];
    const float* bk = (const float*)d_in[7];
    const float* Wv = (const float*)d_in[8];
    const float* bv = (const float*)d_in[9];
    const float* Wo = (const float*)d_in[10];
    const float* bo = (const float*)d_in[11];
    float* out = (float*)d_out;

    float *pQ, *pK, *pV, *pC;
    cudaGetSymbolAddress((void**)&pQ, g_Q);
    cudaGetSymbolAddress((void**)&pK, g_K);
    cudaGetSymbolAddress((void**)&pV, g_V);
    cudaGetSymbolAddress((void**)&pC, g_C);

    // 1) pack mask to bits
    pack_mask_kernel<<<(BATCH * NSEQ * NSEQ) / 256, 256>>>(mask);

    // 2) Q/K/V projections (3xTF32), written directly in (B,H,N,DK)
    dim3 gg(DMODEL / 128, MROWS / 128);
    proj_mma_kernel<true><<<gg, 256>>>(query, Wq, bq, pQ);
    proj_mma_kernel<true><<<gg, 256>>>(key,   Wk, bk, pK);
    proj_mma_kernel<true><<<gg, 256>>>(value, Wv, bv, pV);

    // 3) fused masked attention (tf32 mma, pipelined KV)
    const int attn_smem = (64 * QPAD + 2 * 64 * KPAD) * 4 + 64 * 4; // 54528
    cudaFuncSetAttribute(attn_kernel, cudaFuncAttributeMaxDynamicSharedMemorySize,
                         attn_smem);
    attn_kernel<<<dim3(NSEQ / 64, BATCH * NHEAD), 256, attn_smem>>>();

    // 4) output projection (3xTF32) -> d_out
    proj_mma_kernel<false><<<gg, 256>>>(pC, Wo, bo, out);
}

// round 8
// speedup vs baseline: 1.2082x; 1.2082x over previous
#include <cuda_runtime.h>
#include <cstdint>
#include <cstddef>

// Problem constants
#define BATCH  4
#define NSEQ   2048
#define DMODEL 1024
#define NHEAD  16
#define DKH    64
#define MROWS  (BATCH * NSEQ)   // 8192
#define NEGVAL (-1e11f)

// ---------------- scratch (device globals; no allocation allowed) ----------
__device__ float    g_Q[BATCH * NHEAD * NSEQ * DKH];   // (B,H,N,DK)
__device__ float    g_K[BATCH * NHEAD * NSEQ * DKH];
__device__ float    g_V[BATCH * NHEAD * NSEQ * DKH];
__device__ float    g_C[BATCH * NSEQ * DMODEL];        // attention context (B,N,D)
__device__ unsigned g_pmask[BATCH * NSEQ * NSEQ / 32]; // bit-packed mask

// ---------------- helpers ---------------------------------------------------
__device__ __forceinline__ uint32_t f2tf32(float x) {
    uint32_t r;
    asm("cvt.rna.tf32.f32 %0, %1;" : "=r"(r) : "f"(x));
    return r;
}

__device__ __forceinline__ void mma_tf32(float* c, const uint32_t* a,
                                         uint32_t b0, uint32_t b1) {
    asm volatile(
        "mma.sync.aligned.m16n8k8.row.col.f32.tf32.tf32.f32 "
        "{%0,%1,%2,%3}, {%4,%5,%6,%7}, {%8,%9}, {%0,%1,%2,%3};"
        : "+f"(c[0]), "+f"(c[1]), "+f"(c[2]), "+f"(c[3])
        : "r"(a[0]), "r"(a[1]), "r"(a[2]), "r"(a[3]), "r"(b0), "r"(b1));
}

// ---------------- mask bit-pack: 67MB int32 -> 2MB bits --------------------
__global__ void pack_mask_kernel(const int* __restrict__ mask) {
    int idx = blockIdx.x * blockDim.x + threadIdx.x;
    unsigned bit = (mask[idx] != 0) ? 1u : 0u;
    unsigned w = __ballot_sync(0xffffffffu, bit);
    if ((threadIdx.x & 31) == 0) g_pmask[idx >> 5] = w;
}

// ---------------- projection GEMM: 2xTF32 mma.sync --------------------------
// C(8192x1024) = A @ W + bias.  Block tile 128x128, BK=16, 256 threads (8 warps,
// 2x4 warp grid, warp tile 64x32).  B split-precision (bH + bL); residual error
// ~1.4e-4 (A-lo term dropped) — well inside budget.
template <bool SPLIT>
__global__ __launch_bounds__(256)
void proj_mma_kernel(const float* __restrict__ A, const float* __restrict__ W,
                     const float* __restrict__ bias, float* __restrict__ out) {
    __shared__ uint32_t AsH[16][136];   // [k][m] tf32
    __shared__ uint32_t BsH[16][136];   // [k][n] tf32-hi
    __shared__ uint32_t BsL[16][136];   // [k][n] tf32-lo

    const int tid = threadIdx.x;
    const int w = tid >> 5, l = tid & 31;
    const int lg = l >> 2, lk = l & 3;
    const int wm = (w >> 2) * 64;       // 0,64
    const int wn = (w & 3) * 32;        // 0,32,64,96
    const int m0 = blockIdx.y * 128, n0 = blockIdx.x * 128;

    float c[4][4][4];
#pragma unroll
    for (int mi = 0; mi < 4; ++mi)
#pragma unroll
        for (int nj = 0; nj < 4; ++nj)
#pragma unroll
            for (int t = 0; t < 4; ++t) c[mi][nj][t] = 0.f;

    for (int kt = 0; kt < DMODEL; kt += 16) {
        // prefetch to registers
        float4 av[2], bv[2];
#pragma unroll
        for (int i = 0; i < 2; ++i) {
            int v = tid + 256 * i;
            int am = v & 127, ak4 = (v >> 7) * 4;            // A: row am, k ak4..+3
            av[i] = *(const float4*)(A + (size_t)(m0 + am) * DMODEL + kt + ak4);
            int bk = v >> 5, bn4 = (v & 31) * 4;             // B: row bk, n bn4..+3
            bv[i] = *(const float4*)(W + (size_t)(kt + bk) * DMODEL + n0 + bn4);
        }
        __syncthreads();   // previous tile fully consumed
#pragma unroll
        for (int i = 0; i < 2; ++i) {
            int v = tid + 256 * i;
            int am = v & 127, ak4 = (v >> 7) * 4;
            const float* af = (const float*)&av[i];
#pragma unroll
            for (int j = 0; j < 4; ++j)
                AsH[ak4 + j][am] = f2tf32(af[j]);
            int bk = v >> 5, bn4 = (v & 31) * 4;
            const float* bf = (const float*)&bv[i];
#pragma unroll
            for (int j = 0; j < 4; ++j) {
                uint32_t hi = f2tf32(bf[j]);
                BsH[bk][bn4 + j] = hi;
                BsL[bk][bn4 + j] = f2tf32(bf[j] - __uint_as_float(hi));
            }
        }
        __syncthreads();

#pragma unroll
        for (int ks = 0; ks < 16; ks += 8) {
            uint32_t aH[4][4];
#pragma unroll
            for (int mi = 0; mi < 4; ++mi) {
                int mbase = wm + 16 * mi + lg;
                aH[mi][0] = AsH[ks + lk][mbase];
                aH[mi][1] = AsH[ks + lk][mbase + 8];
                aH[mi][2] = AsH[ks + lk + 4][mbase];
                aH[mi][3] = AsH[ks + lk + 4][mbase + 8];
            }
#pragma unroll
            for (int nj = 0; nj < 4; ++nj) {
                int nb = wn + 8 * nj + lg;
                uint32_t bH0 = BsH[ks + lk][nb], bH1 = BsH[ks + lk + 4][nb];
                uint32_t bL0 = BsL[ks + lk][nb], bL1 = BsL[ks + lk + 4][nb];
#pragma unroll
                for (int mi = 0; mi < 4; ++mi) {
                    mma_tf32(c[mi][nj], aH[mi], bH0, bH1);
                    mma_tf32(c[mi][nj], aH[mi], bL0, bL1);
                }
            }
        }
    }

    // epilogue: bias + store (optionally remapped to (B,H,N,DK))
#pragma unroll
    for (int mi = 0; mi < 4; ++mi) {
#pragma unroll
        for (int nj = 0; nj < 4; ++nj) {
            int col = n0 + wn + 8 * nj + 2 * lk;
            float b0 = __ldg(&bias[col]), b1 = __ldg(&bias[col + 1]);
#pragma unroll
            for (int half = 0; half < 2; ++half) {
                int m = m0 + wm + 16 * mi + lg + 8 * half;
                float2 v;
                v.x = c[mi][nj][2 * half + 0] + b0;
                v.y = c[mi][nj][2 * half + 1] + b1;
                size_t idx;
                if (SPLIT) {
                    int b = m >> 11, row = m & 2047;
                    int h = col >> 6, dk = col & 63;
                    idx = (((size_t)(b * NHEAD + h) * NSEQ + row) * DKH + dk);
                } else {
                    idx = (size_t)m * DMODEL + col;
                }
                *(float2*)&out[idx] = v;
            }
        }
    }
}

// ---------------- fused masked flash attention (tf32 mma) -------------------
// grid: (N/64, B*H), block 256 (8 warps).  64-query tile, 64-key tiles.
// S = Q@K^T via mma -> smem; proven scalar softmax on smem; PV via mma.
// R8: register K/V prefetch reverted (regression in R7); Ps aliases Qs.
#define QPAD 68
#define KPAD 72
__global__ __launch_bounds__(256)
void attn_kernel() {
    extern __shared__ char smraw[];
    uint32_t* Qs = (uint32_t*)smraw;                    // [64][QPAD] (q-major, tf32)
    float*    Ps = (float*)smraw;                       // aliases Qs (dead after preload)
    uint32_t* Ks = (uint32_t*)(smraw + 64 * QPAD * 4);  // [64][KPAD] ([d][key], tf32)
    uint32_t* Vs = (uint32_t*)(smraw + 64 * QPAD * 4 + 64 * KPAD * 4); // [key][KPAD]
    float*    Cr = (float*)(smraw + 64 * QPAD * 4 + 2 * 64 * KPAD * 4); // [64]

    const int tid = threadIdx.x;
    const int w = tid >> 5, l = tid & 31;
    const int lg = l >> 2, lk = l & 3;
    const int rb = (w >> 1) * 16;       // warp row band
    const int cb = (w & 1) * 32;        // warp col half
    const int tx = tid & 15, ty = tid >> 4;
    const int bh = blockIdx.y;
    const int b = bh >> 4;
    const int h = bh & 15;
    const int q0 = blockIdx.x * 64;

    const float* Qg = g_Q + ((size_t)bh * NSEQ + q0) * DKH;
    const float* Kg = g_K + (size_t)bh * NSEQ * DKH;
    const float* Vg = g_V + (size_t)bh * NSEQ * DKH;

    // ---- load Q tile (rounded to tf32), q-major ----
#pragma unroll
    for (int i = 0; i < 4; ++i) {
        int v = tid + 256 * i;
        int row = v >> 4, d4 = (v & 15) * 4;
        float4 q = *(const float4*)(Qg + (size_t)row * DKH + d4);
        Qs[row * QPAD + d4 + 0] = f2tf32(q.x);
        Qs[row * QPAD + d4 + 1] = f2tf32(q.y);
        Qs[row * QPAD + d4 + 2] = f2tf32(q.z);
        Qs[row * QPAD + d4 + 3] = f2tf32(q.w);
    }
    __syncthreads();

    // preload Q fragments (rows rb..rb+15, all 8 k-steps); Qs dead afterwards
    uint32_t qf[8][4];
#pragma unroll
    for (int ks = 0; ks < 8; ++ks) {
        qf[ks][0] = Qs[(rb + lg) * QPAD + ks * 8 + lk];
        qf[ks][1] = Qs[(rb + lg + 8) * QPAD + ks * 8 + lk];
        qf[ks][2] = Qs[(rb + lg) * QPAD + ks * 8 + lk + 4];
        qf[ks][3] = Qs[(rb + lg + 8) * QPAD + ks * 8 + lk + 4];
    }

    // softmax state (owned by the (tx,ty) view threads)
    float m_run[4], l_run[4];
#pragma unroll
    for (int i = 0; i < 4; ++i) { m_run[i] = -1e30f; l_run[i] = 0.f; }

    // PV accumulators (owned by the mma view threads)
    float o[4][4];
#pragma unroll
    for (int nj = 0; nj < 4; ++nj)
#pragma unroll
        for (int t = 0; t < 4; ++t) o[nj][t] = 0.f;

    const int maskRowBase = b * NSEQ + q0;

    for (int kt = 0; kt < NSEQ / 64; ++kt) {
        __syncthreads();   // prior iteration done with Ks/Vs/Ps
        // ---- fill K (transposed [d][key]) and V ([key][dk]), tf32 ----
#pragma unroll
        for (int i = 0; i < 4; ++i) {
            int v = tid + 256 * i;
            {   // K: conflict-free STS layout
                int key = v & 63, d4 = (v >> 6) * 4;
                float4 kv = *(const float4*)(Kg + (size_t)(kt * 64 + key) * DKH + d4);
                Ks[(d4 + 0) * KPAD + key] = f2tf32(kv.x);
                Ks[(d4 + 1) * KPAD + key] = f2tf32(kv.y);
                Ks[(d4 + 2) * KPAD + key] = f2tf32(kv.z);
                Ks[(d4 + 3) * KPAD + key] = f2tf32(kv.w);
            }
            {   // V: coalesced load, natural layout
                int key = v >> 4, d4 = (v & 15) * 4;
                float4 vv = *(const float4*)(Vg + (size_t)(kt * 64 + key) * DKH + d4);
                Vs[key * KPAD + d4 + 0] = f2tf32(vv.x);
                Vs[key * KPAD + d4 + 1] = f2tf32(vv.y);
                Vs[key * KPAD + d4 + 2] = f2tf32(vv.z);
                Vs[key * KPAD + d4 + 3] = f2tf32(vv.w);
            }
        }
        __syncthreads();

        // ---- S = Q @ K^T (mma), store to Ps ----
        {
            float sc[4][4];
#pragma unroll
            for (int nj = 0; nj < 4; ++nj)
#pragma unroll
                for (int t = 0; t < 4; ++t) sc[nj][t] = 0.f;
#pragma unroll
            for (int ks = 0; ks < 8; ++ks) {
#pragma unroll
                for (int nj = 0; nj < 4; ++nj) {
                    int nb = cb + 8 * nj + lg;
                    uint32_t b0 = Ks[(ks * 8 + lk) * KPAD + nb];
                    uint32_t b1 = Ks[(ks * 8 + lk + 4) * KPAD + nb];
                    mma_tf32(sc[nj], qf[ks], b0, b1);
                }
            }
#pragma unroll
            for (int nj = 0; nj < 4; ++nj) {
                int col = cb + 8 * nj + 2 * lk;
                *(float2*)&Ps[(rb + lg) * QPAD + col] = make_float2(sc[nj][0], sc[nj][1]);
                *(float2*)&Ps[(rb + lg + 8) * QPAD + col] = make_float2(sc[nj][2], sc[nj][3]);
            }
        }
        __syncthreads();

        // ---- scalar masked online softmax on Ps ----
        {
            int wcol = kt * 2 + (tx >> 3);
            int bit0 = (4 * tx) & 31;
#pragma unroll
            for (int i = 0; i < 4; ++i) {
                int row = 4 * ty + i;
                float4 sv = *(const float4*)&Ps[row * QPAD + 4 * tx];
                float s[4] = {sv.x, sv.y, sv.z, sv.w};
                unsigned mw = g_pmask[(size_t)(maskRowBase + row) * (NSEQ / 32) + wcol];
                float rm = -1e30f;
#pragma unroll
                for (int j = 0; j < 4; ++j) {
                    float vv = ((mw >> (bit0 + j)) & 1u) ? s[j] * 0.125f : NEGVAL;
                    s[j] = vv;
                    rm = fmaxf(rm, vv);
                }
#pragma unroll
                for (int off = 8; off; off >>= 1)
                    rm = fmaxf(rm, __shfl_xor_sync(0xffffffffu, rm, off));
                float mn = fmaxf(m_run[i], rm);
                float corr = __expf(m_run[i] - mn);
                m_run[i] = mn;
                float p[4], ls = 0.f;
#pragma unroll
                for (int j = 0; j < 4; ++j) {
                    p[j] = __uint_as_float(f2tf32(__expf(s[j] - mn)));
                    ls += p[j];
                }
#pragma unroll
                for (int off = 8; off; off >>= 1)
                    ls += __shfl_xor_sync(0xffffffffu, ls, off);
                l_run[i] = l_run[i] * corr + ls;
                *(float4*)&Ps[row * QPAD + 4 * tx] = make_float4(p[0], p[1], p[2], p[3]);
                if (tx == 0) Cr[row] = corr;
            }
        }
        __syncthreads();

        // ---- O = O*corr + P @ V (mma) ----
        {
            float cr0 = Cr[rb + lg], cr1 = Cr[rb + lg + 8];
#pragma unroll
            for (int nj = 0; nj < 4; ++nj) {
                o[nj][0] *= cr0; o[nj][1] *= cr0;
                o[nj][2] *= cr1; o[nj][3] *= cr1;
            }
#pragma unroll
            for (int ks = 0; ks < 8; ++ks) {
                uint32_t af[4];
                af[0] = __float_as_uint(Ps[(rb + lg) * QPAD + ks * 8 + lk]);
                af[1] = __float_as_uint(Ps[(rb + lg + 8) * QPAD + ks * 8 + lk]);
                af[2] = __float_as_uint(Ps[(rb + lg) * QPAD + ks * 8 + lk + 4]);
                af[3] = __float_as_uint(Ps[(rb + lg + 8) * QPAD + ks * 8 + lk + 4]);
#pragma unroll
                for (int nj = 0; nj < 4; ++nj) {
                    int nb = cb + 8 * nj + lg;
                    uint32_t b0 = Vs[(ks * 8 + lk) * KPAD + nb];
                    uint32_t b1 = Vs[(ks * 8 + lk + 4) * KPAD + nb];
                    mma_tf32(o[nj], af, b0, b1);
                }
            }
        }
    }

    // ---- normalize and write context ----
    __syncthreads();
#pragma unroll
    for (int i = 0; i < 4; ++i)
        if (tx == 0) Cr[4 * ty + i] = 1.0f / l_run[i];
    __syncthreads();

    float inv0 = Cr[rb + lg], inv1 = Cr[rb + lg + 8];
    float* Cg = g_C + ((size_t)(b * NSEQ + q0)) * DMODEL + h * DKH;
#pragma unroll
    for (int nj = 0; nj < 4; ++nj) {
        int col = cb + 8 * nj + 2 * lk;
        *(float2*)&Cg[(size_t)(rb + lg) * DMODEL + col] =
            make_float2(o[nj][0] * inv0, o[nj][1] * inv0);
        *(float2*)&Cg[(size_t)(rb + lg + 8) * DMODEL + col] =
            make_float2(o[nj][2] * inv1, o[nj][3] * inv1);
    }
}

// ---------------- launch ----------------------------------------------------
extern "C" void kernel_launch(void* const* d_in, const int* in_sizes, int n_in,
                              void* d_out, int out_size) {
    const float* query = (const float*)d_in[0];
    const float* key   = (const float*)d_in[1];
    const float* value = (const float*)d_in[2];
    const int*   mask  = (const int*)d_in[3];
    const float* Wq = (const float*)d_in[4];
    const float* bq = (const float*)d_in[5];
    const float* Wk = (const float*)d_in[6];
    const float* bk = (const float*)d_in[7];
    const float* Wv = (const float*)d_in[8];
    const float* bv = (const float*)d_in[9];
    const float* Wo = (const float*)d_in[10];
    const float* bo = (const float*)d_in[11];
    float* out = (float*)d_out;

    float *pQ, *pK, *pV, *pC;
    cudaGetSymbolAddress((void**)&pQ, g_Q);
    cudaGetSymbolAddress((void**)&pK, g_K);
    cudaGetSymbolAddress((void**)&pV, g_V);
    cudaGetSymbolAddress((void**)&pC, g_C);

    // 1) pack mask to bits
    pack_mask_kernel<<<(BATCH * NSEQ * NSEQ) / 256, 256>>>(mask);

    // 2) Q/K/V projections (2xTF32), written directly in (B,H,N,DK)
    dim3 gg(DMODEL / 128, MROWS / 128);
    proj_mma_kernel<true><<<gg, 256>>>(query, Wq, bq, pQ);
    proj_mma_kernel<true><<<gg, 256>>>(key,   Wk, bk, pK);
    proj_mma_kernel<true><<<gg, 256>>>(value, Wv, bv, pV);

    // 3) fused masked attention (tf32 mma)
    const int attn_smem = (64 * QPAD + 2 * 64 * KPAD) * 4 + 64 * 4; // 54528
    cudaFuncSetAttribute(attn_kernel, cudaFuncAttributeMaxDynamicSharedMemorySize,
                         attn_smem);
    attn_kernel<<<dim3(NSEQ / 64, BATCH * NHEAD), 256, attn_smem>>>();

    // 4) output projection (2xTF32) -> d_out
    proj_mma_kernel<false><<<gg, 256>>>(pC, Wo, bo, out);
}

// round 9
// speedup vs baseline: 1.4343x; 1.1872x over previous
#include <cuda_runtime.h>
#include <cstdint>
#include <cstddef>

// Problem constants
#define BATCH  4
#define NSEQ   2048
#define DMODEL 1024
#define NHEAD  16
#define DKH    64
#define MROWS  (BATCH * NSEQ)   // 8192
#define NEGVAL (-1e11f)

// ---------------- scratch (device globals; no allocation allowed) ----------
__device__ float    g_Q[BATCH * NHEAD * NSEQ * DKH];   // (B,H,N,DK)
__device__ float    g_K[BATCH * NHEAD * NSEQ * DKH];
__device__ float    g_V[BATCH * NHEAD * NSEQ * DKH];
__device__ float    g_C[BATCH * NSEQ * DMODEL];        // attention context (B,N,D)
__device__ unsigned g_pmask[BATCH * NSEQ * NSEQ / 32]; // bit-packed mask

// ---------------- helpers ---------------------------------------------------
__device__ __forceinline__ uint32_t f2tf32(float x) {
    uint32_t r;
    asm("cvt.rna.tf32.f32 %0, %1;" : "=r"(r) : "f"(x));
    return r;
}

__device__ __forceinline__ void mma_tf32(float* c, const uint32_t* a,
                                         uint32_t b0, uint32_t b1) {
    asm volatile(
        "mma.sync.aligned.m16n8k8.row.col.f32.tf32.tf32.f32 "
        "{%0,%1,%2,%3}, {%4,%5,%6,%7}, {%8,%9}, {%0,%1,%2,%3};"
        : "+f"(c[0]), "+f"(c[1]), "+f"(c[2]), "+f"(c[3])
        : "r"(a[0]), "r"(a[1]), "r"(a[2]), "r"(a[3]), "r"(b0), "r"(b1));
}

__device__ __forceinline__ void cp16(uint32_t dst, const float* src) {
    asm volatile("cp.async.ca.shared.global [%0], [%1], 16;\n"
                 :: "r"(dst), "l"(src));
}
__device__ __forceinline__ void cp_commit() {
    asm volatile("cp.async.commit_group;\n");
}
template <int N>
__device__ __forceinline__ void cp_wait() {
    asm volatile("cp.async.wait_group %0;\n" :: "n"(N));
}

// ---------------- mask bit-pack: 67MB int32 -> 2MB bits --------------------
__global__ void pack_mask_kernel(const int* __restrict__ mask) {
    int idx = blockIdx.x * blockDim.x + threadIdx.x;
    unsigned bit = (mask[idx] != 0) ? 1u : 0u;
    unsigned w = __ballot_sync(0xffffffffu, bit);
    if ((threadIdx.x & 31) == 0) g_pmask[idx >> 5] = w;
}

// ---------------- projection GEMM core: 2xTF32 + cp.async pipeline ----------
// C(8192x1024) = A @ W + bias.  Block tile 128x128, BK=16, 256 threads (8 warps,
// 2x4 warp grid, warp tile 64x32).  Raw fp32 in smem; tf32 split at frag load.
// Double-buffered cp.async, 2 tiles in flight.
#define AST 20    // A smem row stride (floats): conflict-free, 16B aligned
#define BST 136   // B smem row stride (floats): conflict-free, 16B aligned

template <bool SPLIT>
__device__ __forceinline__ void proj_core(const float* __restrict__ A,
                                          const float* __restrict__ W,
                                          const float* __restrict__ bias,
                                          float* __restrict__ out) {
    __shared__ float sA[2][128 * AST];   // [m][k] raw fp32
    __shared__ float sB[2][16 * BST];    // [k][n] raw fp32

    const int tid = threadIdx.x;
    const int w = tid >> 5, l = tid & 31;
    const int lg = l >> 2, lk = l & 3;
    const int wm = (w >> 2) * 64;       // 0,64
    const int wn = (w & 3) * 32;        // 0,32,64,96
    const int m0 = blockIdx.y * 128, n0 = blockIdx.x * 128;

    const uint32_t sAaddr0 = (uint32_t)__cvta_generic_to_shared(&sA[0][0]);
    const uint32_t sAaddr1 = (uint32_t)__cvta_generic_to_shared(&sA[1][0]);
    const uint32_t sBaddr0 = (uint32_t)__cvta_generic_to_shared(&sB[0][0]);
    const uint32_t sBaddr1 = (uint32_t)__cvta_generic_to_shared(&sB[1][0]);

    // chunk coordinates (2 x 16B for A, 2 x 16B for B per thread per tile)
    const int ac0 = tid, ac1 = tid + 256;            // A: 512 chunks (128r x 4)
    const int ar0 = ac0 >> 2, ao0 = (ac0 & 3) * 4;
    const int ar1 = ac1 >> 2, ao1 = (ac1 & 3) * 4;
    const int bc0 = tid, bc1 = tid + 256;            // B: 512 chunks (16r x 32)
    const int br0 = bc0 >> 5, bo0 = (bc0 & 31) * 4;
    const int br1 = bc1 >> 5, bo1 = (bc1 & 31) * 4;

    auto load_tile = [&](int kt, int buf) {
        uint32_t sa = buf ? sAaddr1 : sAaddr0;
        uint32_t sb = buf ? sBaddr1 : sBaddr0;
        cp16(sa + (ar0 * AST + ao0) * 4, A + (size_t)(m0 + ar0) * DMODEL + kt + ao0);
        cp16(sa + (ar1 * AST + ao1) * 4, A + (size_t)(m0 + ar1) * DMODEL + kt + ao1);
        cp16(sb + (br0 * BST + bo0) * 4, W + (size_t)(kt + br0) * DMODEL + n0 + bo0);
        cp16(sb + (br1 * BST + bo1) * 4, W + (size_t)(kt + br1) * DMODEL + n0 + bo1);
        cp_commit();
    };

    float c[4][4][4];
#pragma unroll
    for (int mi = 0; mi < 4; ++mi)
#pragma unroll
        for (int nj = 0; nj < 4; ++nj)
#pragma unroll
            for (int t = 0; t < 4; ++t) c[mi][nj][t] = 0.f;

    // prologue: two tiles in flight
    load_tile(0, 0);
    load_tile(16, 1);

    for (int it = 0; it < DMODEL / 16; ++it) {
        const float* cA = sA[it & 1];
        const float* cB = sB[it & 1];
        cp_wait<1>();          // current tile landed
        __syncthreads();       // visible to all warps

#pragma unroll
        for (int ks = 0; ks < 16; ks += 8) {
            uint32_t aH[4][4];
#pragma unroll
            for (int mi = 0; mi < 4; ++mi) {
                int mbase = wm + 16 * mi + lg;
                aH[mi][0] = f2tf32(cA[mbase * AST + ks + lk]);
                aH[mi][1] = f2tf32(cA[(mbase + 8) * AST + ks + lk]);
                aH[mi][2] = f2tf32(cA[mbase * AST + ks + lk + 4]);
                aH[mi][3] = f2tf32(cA[(mbase + 8) * AST + ks + lk + 4]);
            }
#pragma unroll
            for (int nj = 0; nj < 4; ++nj) {
                int nb = wn + 8 * nj + lg;
                float b0r = cB[(ks + lk) * BST + nb];
                float b1r = cB[(ks + lk + 4) * BST + nb];
                uint32_t bH0 = f2tf32(b0r), bH1 = f2tf32(b1r);
                uint32_t bL0 = __float_as_uint(b0r - __uint_as_float(bH0));
                uint32_t bL1 = __float_as_uint(b1r - __uint_as_float(bH1));
#pragma unroll
                for (int mi = 0; mi < 4; ++mi) {
                    mma_tf32(c[mi][nj], aH[mi], bH0, bH1);
                    mma_tf32(c[mi][nj], aH[mi], bL0, bL1);
                }
            }
        }
        __syncthreads();       // all warps done with this buffer
        if (it + 2 < DMODEL / 16) load_tile((it + 2) * 16, it & 1);
        else cp_commit();      // keep group count in step
    }

    // epilogue: bias + store (optionally remapped to (B,H,N,DK))
#pragma unroll
    for (int mi = 0; mi < 4; ++mi) {
#pragma unroll
        for (int nj = 0; nj < 4; ++nj) {
            int col = n0 + wn + 8 * nj + 2 * lk;
            float b0 = __ldg(&bias[col]), b1 = __ldg(&bias[col + 1]);
#pragma unroll
            for (int half = 0; half < 2; ++half) {
                int m = m0 + wm + 16 * mi + lg + 8 * half;
                float2 v;
                v.x = c[mi][nj][2 * half + 0] + b0;
                v.y = c[mi][nj][2 * half + 1] + b1;
                size_t idx;
                if (SPLIT) {
                    int b = m >> 11, row = m & 2047;
                    int h = col >> 6, dk = col & 63;
                    idx = (((size_t)(b * NHEAD + h) * NSEQ + row) * DKH + dk);
                } else {
                    idx = (size_t)m * DMODEL + col;
                }
                *(float2*)&out[idx] = v;
            }
        }
    }
}

// merged Q/K/V projections: gridDim.z = 3 selects the (input, weight, bias, out)
__global__ __launch_bounds__(256)
void proj_qkv_kernel(const float* __restrict__ q, const float* __restrict__ k,
                     const float* __restrict__ v,
                     const float* __restrict__ Wq, const float* __restrict__ Wk,
                     const float* __restrict__ Wv,
                     const float* __restrict__ bq, const float* __restrict__ bk,
                     const float* __restrict__ bv,
                     float* __restrict__ oq, float* __restrict__ ok,
                     float* __restrict__ ov) {
    const float *A, *W, *bias;
    float* out;
    if (blockIdx.z == 0)      { A = q; W = Wq; bias = bq; out = oq; }
    else if (blockIdx.z == 1) { A = k; W = Wk; bias = bk; out = ok; }
    else                      { A = v; W = Wv; bias = bv; out = ov; }
    proj_core<true>(A, W, bias, out);
}

__global__ __launch_bounds__(256)
void proj_out_kernel(const float* __restrict__ A, const float* __restrict__ W,
                     const float* __restrict__ bias, float* __restrict__ out) {
    proj_core<false>(A, W, bias, out);
}

// ---------------- fused masked flash attention (tf32 mma) -------------------
// grid: (N/64, B*H), block 256 (8 warps).  64-query tile, 64-key tiles.
// S = Q@K^T via mma -> smem; proven scalar softmax on smem; PV via mma.
// (unchanged from R8 best)
#define QPAD 68
#define KPAD 72
__global__ __launch_bounds__(256)
void attn_kernel() {
    extern __shared__ char smraw[];
    uint32_t* Qs = (uint32_t*)smraw;                    // [64][QPAD] (q-major, tf32)
    float*    Ps = (float*)smraw;                       // aliases Qs (dead after preload)
    uint32_t* Ks = (uint32_t*)(smraw + 64 * QPAD * 4);  // [64][KPAD] ([d][key], tf32)
    uint32_t* Vs = (uint32_t*)(smraw + 64 * QPAD * 4 + 64 * KPAD * 4); // [key][KPAD]
    float*    Cr = (float*)(smraw + 64 * QPAD * 4 + 2 * 64 * KPAD * 4); // [64]

    const int tid = threadIdx.x;
    const int w = tid >> 5, l = tid & 31;
    const int lg = l >> 2, lk = l & 3;
    const int rb = (w >> 1) * 16;       // warp row band
    const int cb = (w & 1) * 32;        // warp col half
    const int tx = tid & 15, ty = tid >> 4;
    const int bh = blockIdx.y;
    const int b = bh >> 4;
    const int h = bh & 15;
    const int q0 = blockIdx.x * 64;

    const float* Qg = g_Q + ((size_t)bh * NSEQ + q0) * DKH;
    const float* Kg = g_K + (size_t)bh * NSEQ * DKH;
    const float* Vg = g_V + (size_t)bh * NSEQ * DKH;

    // ---- load Q tile (rounded to tf32), q-major ----
#pragma unroll
    for (int i = 0; i < 4; ++i) {
        int v = tid + 256 * i;
        int row = v >> 4, d4 = (v & 15) * 4;
        float4 q = *(const float4*)(Qg + (size_t)row * DKH + d4);
        Qs[row * QPAD + d4 + 0] = f2tf32(q.x);
        Qs[row * QPAD + d4 + 1] = f2tf32(q.y);
        Qs[row * QPAD + d4 + 2] = f2tf32(q.z);
        Qs[row * QPAD + d4 + 3] = f2tf32(q.w);
    }
    __syncthreads();

    // preload Q fragments (rows rb..rb+15, all 8 k-steps); Qs dead afterwards
    uint32_t qf[8][4];
#pragma unroll
    for (int ks = 0; ks < 8; ++ks) {
        qf[ks][0] = Qs[(rb + lg) * QPAD + ks * 8 + lk];
        qf[ks][1] = Qs[(rb + lg + 8) * QPAD + ks * 8 + lk];
        qf[ks][2] = Qs[(rb + lg) * QPAD + ks * 8 + lk + 4];
        qf[ks][3] = Qs[(rb + lg + 8) * QPAD + ks * 8 + lk + 4];
    }

    // softmax state (owned by the (tx,ty) view threads)
    float m_run[4], l_run[4];
#pragma unroll
    for (int i = 0; i < 4; ++i) { m_run[i] = -1e30f; l_run[i] = 0.f; }

    // PV accumulators (owned by the mma view threads)
    float o[4][4];
#pragma unroll
    for (int nj = 0; nj < 4; ++nj)
#pragma unroll
        for (int t = 0; t < 4; ++t) o[nj][t] = 0.f;

    const int maskRowBase = b * NSEQ + q0;

    for (int kt = 0; kt < NSEQ / 64; ++kt) {
        __syncthreads();   // prior iteration done with Ks/Vs/Ps
        // ---- fill K (transposed [d][key]) and V ([key][dk]), tf32 ----
#pragma unroll
        for (int i = 0; i < 4; ++i) {
            int v = tid + 256 * i;
            {   // K: conflict-free STS layout
                int key = v & 63, d4 = (v >> 6) * 4;
                float4 kv = *(const float4*)(Kg + (size_t)(kt * 64 + key) * DKH + d4);
                Ks[(d4 + 0) * KPAD + key] = f2tf32(kv.x);
                Ks[(d4 + 1) * KPAD + key] = f2tf32(kv.y);
                Ks[(d4 + 2) * KPAD + key] = f2tf32(kv.z);
                Ks[(d4 + 3) * KPAD + key] = f2tf32(kv.w);
            }
            {   // V: coalesced load, natural layout
                int key = v >> 4, d4 = (v & 15) * 4;
                float4 vv = *(const float4*)(Vg + (size_t)(kt * 64 + key) * DKH + d4);
                Vs[key * KPAD + d4 + 0] = f2tf32(vv.x);
                Vs[key * KPAD + d4 + 1] = f2tf32(vv.y);
                Vs[key * KPAD + d4 + 2] = f2tf32(vv.z);
                Vs[key * KPAD + d4 + 3] = f2tf32(vv.w);
            }
        }
        __syncthreads();

        // ---- S = Q @ K^T (mma), store to Ps ----
        {
            float sc[4][4];
#pragma unroll
            for (int nj = 0; nj < 4; ++nj)
#pragma unroll
                for (int t = 0; t < 4; ++t) sc[nj][t] = 0.f;
#pragma unroll
            for (int ks = 0; ks < 8; ++ks) {
#pragma unroll
                for (int nj = 0; nj < 4; ++nj) {
                    int nb = cb + 8 * nj + lg;
                    uint32_t b0 = Ks[(ks * 8 + lk) * KPAD + nb];
                    uint32_t b1 = Ks[(ks * 8 + lk + 4) * KPAD + nb];
                    mma_tf32(sc[nj], qf[ks], b0, b1);
                }
            }
#pragma unroll
            for (int nj = 0; nj < 4; ++nj) {
                int col = cb + 8 * nj + 2 * lk;
                *(float2*)&Ps[(rb + lg) * QPAD + col] = make_float2(sc[nj][0], sc[nj][1]);
                *(float2*)&Ps[(rb + lg + 8) * QPAD + col] = make_float2(sc[nj][2], sc[nj][3]);
            }
        }
        __syncthreads();

        // ---- scalar masked online softmax on Ps ----
        {
            int wcol = kt * 2 + (tx >> 3);
            int bit0 = (4 * tx) & 31;
#pragma unroll
            for (int i = 0; i < 4; ++i) {
                int row = 4 * ty + i;
                float4 sv = *(const float4*)&Ps[row * QPAD + 4 * tx];
                float s[4] = {sv.x, sv.y, sv.z, sv.w};
                unsigned mw = g_pmask[(size_t)(maskRowBase + row) * (NSEQ / 32) + wcol];
                float rm = -1e30f;
#pragma unroll
                for (int j = 0; j < 4; ++j) {
                    float vv = ((mw >> (bit0 + j)) & 1u) ? s[j] * 0.125f : NEGVAL;
                    s[j] = vv;
                    rm = fmaxf(rm, vv);
                }
#pragma unroll
                for (int off = 8; off; off >>= 1)
                    rm = fmaxf(rm, __shfl_xor_sync(0xffffffffu, rm, off));
                float mn = fmaxf(m_run[i], rm);
                float corr = __expf(m_run[i] - mn);
                m_run[i] = mn;
                float p[4], ls = 0.f;
#pragma unroll
                for (int j = 0; j < 4; ++j) {
                    p[j] = __uint_as_float(f2tf32(__expf(s[j] - mn)));
                    ls += p[j];
                }
#pragma unroll
                for (int off = 8; off; off >>= 1)
                    ls += __shfl_xor_sync(0xffffffffu, ls, off);
                l_run[i] = l_run[i] * corr + ls;
                *(float4*)&Ps[row * QPAD + 4 * tx] = make_float4(p[0], p[1], p[2], p[3]);
                if (tx == 0) Cr[row] = corr;
            }
        }
        __syncthreads();

        // ---- O = O*corr + P @ V (mma) ----
        {
            float cr0 = Cr[rb + lg], cr1 = Cr[rb + lg + 8];
#pragma unroll
            for (int nj = 0; nj < 4; ++nj) {
                o[nj][0] *= cr0; o[nj][1] *= cr0;
                o[nj][2] *= cr1; o[nj][3] *= cr1;
            }
#pragma unroll
            for (int ks = 0; ks < 8; ++ks) {
                uint32_t af[4];
                af[0] = __float_as_uint(Ps[(rb + lg) * QPAD + ks * 8 + lk]);
                af[1] = __float_as_uint(Ps[(rb + lg + 8) * QPAD + ks * 8 + lk]);
                af[2] = __float_as_uint(Ps[(rb + lg) * QPAD + ks * 8 + lk + 4]);
                af[3] = __float_as_uint(Ps[(rb + lg + 8) * QPAD + ks * 8 + lk + 4]);
#pragma unroll
                for (int nj = 0; nj < 4; ++nj) {
                    int nb = cb + 8 * nj + lg;
                    uint32_t b0 = Vs[(ks * 8 + lk) * KPAD + nb];
                    uint32_t b1 = Vs[(ks * 8 + lk + 4) * KPAD + nb];
                    mma_tf32(o[nj], af, b0, b1);
                }
            }
        }
    }

    // ---- normalize and write context ----
    __syncthreads();
#pragma unroll
    for (int i = 0; i < 4; ++i)
        if (tx == 0) Cr[4 * ty + i] = 1.0f / l_run[i];
    __syncthreads();

    float inv0 = Cr[rb + lg], inv1 = Cr[rb + lg + 8];
    float* Cg = g_C + ((size_t)(b * NSEQ + q0)) * DMODEL + h * DKH;
#pragma unroll
    for (int nj = 0; nj < 4; ++nj) {
        int col = cb + 8 * nj + 2 * lk;
        *(float2*)&Cg[(size_t)(rb + lg) * DMODEL + col] =
            make_float2(o[nj][0] * inv0, o[nj][1] * inv0);
        *(float2*)&Cg[(size_t)(rb + lg + 8) * DMODEL + col] =
            make_float2(o[nj][2] * inv1, o[nj][3] * inv1);
    }
}

// ---------------- launch ----------------------------------------------------
extern "C" void kernel_launch(void* const* d_in, const int* in_sizes, int n_in,
                              void* d_out, int out_size) {
    const float* query = (const float*)d_in[0];
    const float* key   = (const float*)d_in[1];
    const float* value = (const float*)d_in[2];
    const int*   mask  = (const int*)d_in[3];
    const float* Wq = (const float*)d_in[4];
    const float* bq = (const float*)d_in[5];
    const float* Wk = (const float*)d_in[6];
    const float* bk = (const float*)d_in[7];
    const float* Wv = (const float*)d_in[8];
    const float* bv = (const float*)d_in[9];
    const float* Wo = (const float*)d_in[10];
    const float* bo = (const float*)d_in[11];
    float* out = (float*)d_out;

    float *pQ, *pK, *pV, *pC;
    cudaGetSymbolAddress((void**)&pQ, g_Q);
    cudaGetSymbolAddress((void**)&pK, g_K);
    cudaGetSymbolAddress((void**)&pV, g_V);
    cudaGetSymbolAddress((void**)&pC, g_C);

    // 1) pack mask to bits
    pack_mask_kernel<<<(BATCH * NSEQ * NSEQ) / 256, 256>>>(mask);

    // 2) Q/K/V projections (2xTF32, cp.async pipelined), one merged launch
    dim3 gq(DMODEL / 128, MROWS / 128, 3);
    proj_qkv_kernel<<<gq, 256>>>(query, key, value, Wq, Wk, Wv,
                                 bq, bk, bv, pQ, pK, pV);

    // 3) fused masked attention (tf32 mma)
    const int attn_smem = (64 * QPAD + 2 * 64 * KPAD) * 4 + 64 * 4; // 54528
    cudaFuncSetAttribute(attn_kernel, cudaFuncAttributeMaxDynamicSharedMemorySize,
                         attn_smem);
    attn_kernel<<<dim3(NSEQ / 64, BATCH * NHEAD), 256, attn_smem>>>();

    // 4) output projection (2xTF32, cp.async pipelined) -> d_out
    dim3 go(DMODEL / 128, MROWS / 128);
    proj_out_kernel<<<go, 256>>>(pC, Wo, bo, out);
}

// round 10
// speedup vs baseline: 1.6233x; 1.1318x over previous
#include <cuda_runtime.h>
#include <cstdint>
#include <cstddef>

// Problem constants
#define BATCH  4
#define NSEQ   2048
#define DMODEL 1024
#define NHEAD  16
#define DKH    64
#define MROWS  (BATCH * NSEQ)   // 8192
#define NEGVAL (-1e11f)

// ---------------- scratch (device globals; no allocation allowed) ----------
__device__ float    g_Q[BATCH * NHEAD * NSEQ * DKH];   // (B,H,N,DK)
__device__ float    g_K[BATCH * NHEAD * NSEQ * DKH];
__device__ float    g_V[BATCH * NHEAD * NSEQ * DKH];
__device__ float    g_C[BATCH * NSEQ * DMODEL];        // attention context (B,N,D)
__device__ unsigned g_pmask[BATCH * NSEQ * NSEQ / 32]; // bit-packed mask

// ---------------- helpers ---------------------------------------------------
__device__ __forceinline__ uint32_t f2tf32(float x) {
    uint32_t r;
    asm("cvt.rna.tf32.f32 %0, %1;" : "=r"(r) : "f"(x));
    return r;
}

__device__ __forceinline__ void mma_tf32(float* c, const uint32_t* a,
                                         uint32_t b0, uint32_t b1) {
    asm volatile(
        "mma.sync.aligned.m16n8k8.row.col.f32.tf32.tf32.f32 "
        "{%0,%1,%2,%3}, {%4,%5,%6,%7}, {%8,%9}, {%0,%1,%2,%3};"
        : "+f"(c[0]), "+f"(c[1]), "+f"(c[2]), "+f"(c[3])
        : "r"(a[0]), "r"(a[1]), "r"(a[2]), "r"(a[3]), "r"(b0), "r"(b1));
}

__device__ __forceinline__ void cp16(uint32_t dst, const float* src) {
    asm volatile("cp.async.ca.shared.global [%0], [%1], 16;\n"
                 :: "r"(dst), "l"(src));
}
__device__ __forceinline__ void cp_commit() {
    asm volatile("cp.async.commit_group;\n");
}
template <int N>
__device__ __forceinline__ void cp_wait() {
    asm volatile("cp.async.wait_group %0;\n" :: "n"(N));
}

// ---------------- mask bit-pack: 67MB int32 -> 2MB bits --------------------
__global__ void pack_mask_kernel(const int* __restrict__ mask) {
    int idx = blockIdx.x * blockDim.x + threadIdx.x;
    unsigned bit = (mask[idx] != 0) ? 1u : 0u;
    unsigned w = __ballot_sync(0xffffffffu, bit);
    if ((threadIdx.x & 31) == 0) g_pmask[idx >> 5] = w;
}

// ---------------- projection GEMM core: 2xTF32 + cp.async pipeline ----------
// (unchanged from R9 best)
#define AST 20    // A smem row stride (floats)
#define BST 136   // B smem row stride (floats)

template <bool SPLIT>
__device__ __forceinline__ void proj_core(const float* __restrict__ A,
                                          const float* __restrict__ W,
                                          const float* __restrict__ bias,
                                          float* __restrict__ out) {
    __shared__ float sA[2][128 * AST];   // [m][k] raw fp32
    __shared__ float sB[2][16 * BST];    // [k][n] raw fp32

    const int tid = threadIdx.x;
    const int w = tid >> 5, l = tid & 31;
    const int lg = l >> 2, lk = l & 3;
    const int wm = (w >> 2) * 64;       // 0,64
    const int wn = (w & 3) * 32;        // 0,32,64,96
    const int m0 = blockIdx.y * 128, n0 = blockIdx.x * 128;

    const uint32_t sAaddr0 = (uint32_t)__cvta_generic_to_shared(&sA[0][0]);
    const uint32_t sAaddr1 = (uint32_t)__cvta_generic_to_shared(&sA[1][0]);
    const uint32_t sBaddr0 = (uint32_t)__cvta_generic_to_shared(&sB[0][0]);
    const uint32_t sBaddr1 = (uint32_t)__cvta_generic_to_shared(&sB[1][0]);

    const int ac0 = tid, ac1 = tid + 256;
    const int ar0 = ac0 >> 2, ao0 = (ac0 & 3) * 4;
    const int ar1 = ac1 >> 2, ao1 = (ac1 & 3) * 4;
    const int bc0 = tid, bc1 = tid + 256;
    const int br0 = bc0 >> 5, bo0 = (bc0 & 31) * 4;
    const int br1 = bc1 >> 5, bo1 = (bc1 & 31) * 4;

    auto load_tile = [&](int kt, int buf) {
        uint32_t sa = buf ? sAaddr1 : sAaddr0;
        uint32_t sb = buf ? sBaddr1 : sBaddr0;
        cp16(sa + (ar0 * AST + ao0) * 4, A + (size_t)(m0 + ar0) * DMODEL + kt + ao0);
        cp16(sa + (ar1 * AST + ao1) * 4, A + (size_t)(m0 + ar1) * DMODEL + kt + ao1);
        cp16(sb + (br0 * BST + bo0) * 4, W + (size_t)(kt + br0) * DMODEL + n0 + bo0);
        cp16(sb + (br1 * BST + bo1) * 4, W + (size_t)(kt + br1) * DMODEL + n0 + bo1);
        cp_commit();
    };

    float c[4][4][4];
#pragma unroll
    for (int mi = 0; mi < 4; ++mi)
#pragma unroll
        for (int nj = 0; nj < 4; ++nj)
#pragma unroll
            for (int t = 0; t < 4; ++t) c[mi][nj][t] = 0.f;

    load_tile(0, 0);
    load_tile(16, 1);

    for (int it = 0; it < DMODEL / 16; ++it) {
        const float* cA = sA[it & 1];
        const float* cB = sB[it & 1];
        cp_wait<1>();
        __syncthreads();

#pragma unroll
        for (int ks = 0; ks < 16; ks += 8) {
            uint32_t aH[4][4];
#pragma unroll
            for (int mi = 0; mi < 4; ++mi) {
                int mbase = wm + 16 * mi + lg;
                aH[mi][0] = f2tf32(cA[mbase * AST + ks + lk]);
                aH[mi][1] = f2tf32(cA[(mbase + 8) * AST + ks + lk]);
                aH[mi][2] = f2tf32(cA[mbase * AST + ks + lk + 4]);
                aH[mi][3] = f2tf32(cA[(mbase + 8) * AST + ks + lk + 4]);
            }
#pragma unroll
            for (int nj = 0; nj < 4; ++nj) {
                int nb = wn + 8 * nj + lg;
                float b0r = cB[(ks + lk) * BST + nb];
                float b1r = cB[(ks + lk + 4) * BST + nb];
                uint32_t bH0 = f2tf32(b0r), bH1 = f2tf32(b1r);
                uint32_t bL0 = __float_as_uint(b0r - __uint_as_float(bH0));
                uint32_t bL1 = __float_as_uint(b1r - __uint_as_float(bH1));
#pragma unroll
                for (int mi = 0; mi < 4; ++mi) {
                    mma_tf32(c[mi][nj], aH[mi], bH0, bH1);
                    mma_tf32(c[mi][nj], aH[mi], bL0, bL1);
                }
            }
        }
        __syncthreads();
        if (it + 2 < DMODEL / 16) load_tile((it + 2) * 16, it & 1);
        else cp_commit();
    }

#pragma unroll
    for (int mi = 0; mi < 4; ++mi) {
#pragma unroll
        for (int nj = 0; nj < 4; ++nj) {
            int col = n0 + wn + 8 * nj + 2 * lk;
            float b0 = __ldg(&bias[col]), b1 = __ldg(&bias[col + 1]);
#pragma unroll
            for (int half = 0; half < 2; ++half) {
                int m = m0 + wm + 16 * mi + lg + 8 * half;
                float2 v;
                v.x = c[mi][nj][2 * half + 0] + b0;
                v.y = c[mi][nj][2 * half + 1] + b1;
                size_t idx;
                if (SPLIT) {
                    int b = m >> 11, row = m & 2047;
                    int h = col >> 6, dk = col & 63;
                    idx = (((size_t)(b * NHEAD + h) * NSEQ + row) * DKH + dk);
                } else {
                    idx = (size_t)m * DMODEL + col;
                }
                *(float2*)&out[idx] = v;
            }
        }
    }
}

__global__ __launch_bounds__(256)
void proj_qkv_kernel(const float* __restrict__ q, const float* __restrict__ k,
                     const float* __restrict__ v,
                     const float* __restrict__ Wq, const float* __restrict__ Wk,
                     const float* __restrict__ Wv,
                     const float* __restrict__ bq, const float* __restrict__ bk,
                     const float* __restrict__ bv,
                     float* __restrict__ oq, float* __restrict__ ok,
                     float* __restrict__ ov) {
    const float *A, *W, *bias;
    float* out;
    if (blockIdx.z == 0)      { A = q; W = Wq; bias = bq; out = oq; }
    else if (blockIdx.z == 1) { A = k; W = Wk; bias = bk; out = ok; }
    else                      { A = v; W = Wv; bias = bv; out = ov; }
    proj_core<true>(A, W, bias, out);
}

__global__ __launch_bounds__(256)
void proj_out_kernel(const float* __restrict__ A, const float* __restrict__ W,
                     const float* __restrict__ bias, float* __restrict__ out) {
    proj_core<false>(A, W, bias, out);
}

// ---------------- fused masked flash attention (tf32 mma, fragment softmax) -
// R10: 128-query tile, 8 warps, each warp owns 16 rows x all 64 key cols.
// Softmax runs in the mma fragment view: row reductions = 2 shfl within the
// 4-lane lk-group; corr applies directly to O accumulators. S never touches
// smem; P staged to warp-private smem rows (syncwarp only). 2 block barriers
// per key-tile (vs 8 per 128 queries before).
#define QPAD 68
#define KPAD 72
__global__ __launch_bounds__(256)
void attn_kernel() {
    extern __shared__ char smraw[];
    uint32_t* Qs = (uint32_t*)smraw;                       // [128][QPAD] tf32
    float*    Ps = (float*)smraw;                          // aliases Qs
    uint32_t* Ks = (uint32_t*)(smraw + 128 * QPAD * 4);    // [d=64][key KPAD]
    uint32_t* Vs = (uint32_t*)(smraw + 128 * QPAD * 4 + 64 * KPAD * 4); // [key][dk KPAD]
    unsigned* Ms = (unsigned*)(smraw + 128 * QPAD * 4 + 2 * 64 * KPAD * 4); // [128][2]

    const int tid = threadIdx.x;
    const int w = tid >> 5, l = tid & 31;
    const int lg = l >> 2, lk = l & 3;
    const int rb = w * 16;              // warp row band (16 rows)
    const int bh = blockIdx.y;
    const int b = bh >> 4;
    const int h = bh & 15;
    const int q0 = blockIdx.x * 128;

    const float* Qg = g_Q + ((size_t)bh * NSEQ + q0) * DKH;
    const float* Kg = g_K + (size_t)bh * NSEQ * DKH;
    const float* Vg = g_V + (size_t)bh * NSEQ * DKH;

    // ---- load Q tile (tf32), q-major ----
#pragma unroll
    for (int i = 0; i < 8; ++i) {
        int v = tid + 256 * i;
        int row = v >> 4, d4 = (v & 15) * 4;
        float4 q = *(const float4*)(Qg + (size_t)row * DKH + d4);
        Qs[row * QPAD + d4 + 0] = f2tf32(q.x);
        Qs[row * QPAD + d4 + 1] = f2tf32(q.y);
        Qs[row * QPAD + d4 + 2] = f2tf32(q.z);
        Qs[row * QPAD + d4 + 3] = f2tf32(q.w);
    }
    __syncthreads();

    // preload Q fragments (rows rb..rb+15, all 8 k-steps); Qs dead afterwards
    uint32_t qf[8][4];
#pragma unroll
    for (int ks = 0; ks < 8; ++ks) {
        qf[ks][0] = Qs[(rb + lg) * QPAD + ks * 8 + lk];
        qf[ks][1] = Qs[(rb + lg + 8) * QPAD + ks * 8 + lk];
        qf[ks][2] = Qs[(rb + lg) * QPAD + ks * 8 + lk + 4];
        qf[ks][3] = Qs[(rb + lg + 8) * QPAD + ks * 8 + lk + 4];
    }

    // softmax state: thread owns rows rb+lg (idx 0) and rb+lg+8 (idx 1)
    float m_run[2] = {-1e30f, -1e30f};
    float l_run[2] = {0.f, 0.f};

    // PV accumulators: o[nj] rows (lg, lg+8) x cols (8nj+2lk, +1)
    float o[8][4];
#pragma unroll
    for (int nj = 0; nj < 8; ++nj)
#pragma unroll
        for (int t = 0; t < 4; ++t) o[nj][t] = 0.f;

    const int maskRowBase = b * NSEQ + q0;

    for (int kt = 0; kt < NSEQ / 64; ++kt) {
        __syncthreads();   // prior iteration done with Ks/Vs/Ms
        // ---- fill K (transposed [d][key]), V ([key][dk]), mask words ----
#pragma unroll
        for (int i = 0; i < 4; ++i) {
            int v = tid + 256 * i;
            {   // K
                int key = v & 63, d4 = (v >> 6) * 4;
                float4 kv = *(const float4*)(Kg + (size_t)(kt * 64 + key) * DKH + d4);
                Ks[(d4 + 0) * KPAD + key] = f2tf32(kv.x);
                Ks[(d4 + 1) * KPAD + key] = f2tf32(kv.y);
                Ks[(d4 + 2) * KPAD + key] = f2tf32(kv.z);
                Ks[(d4 + 3) * KPAD + key] = f2tf32(kv.w);
            }
            {   // V
                int key = v >> 4, d4 = (v & 15) * 4;
                float4 vv = *(const float4*)(Vg + (size_t)(kt * 64 + key) * DKH + d4);
                Vs[key * KPAD + d4 + 0] = f2tf32(vv.x);
                Vs[key * KPAD + d4 + 1] = f2tf32(vv.y);
                Vs[key * KPAD + d4 + 2] = f2tf32(vv.z);
                Vs[key * KPAD + d4 + 3] = f2tf32(vv.w);
            }
        }
        Ms[tid] = g_pmask[(size_t)(maskRowBase + (tid >> 1)) * (NSEQ / 32)
                          + kt * 2 + (tid & 1)];
        __syncthreads();

        // ---- S = Q @ K^T (mma, registers only) ----
        float sc[8][4];
#pragma unroll
        for (int nj = 0; nj < 8; ++nj)
#pragma unroll
            for (int t = 0; t < 4; ++t) sc[nj][t] = 0.f;
#pragma unroll
        for (int ks = 0; ks < 8; ++ks) {
#pragma unroll
            for (int nj = 0; nj < 8; ++nj) {
                int nb = 8 * nj + lg;
                uint32_t b0 = Ks[(ks * 8 + lk) * KPAD + nb];
                uint32_t b1 = Ks[(ks * 8 + lk + 4) * KPAD + nb];
                mma_tf32(sc[nj], qf[ks], b0, b1);
            }
        }

        // ---- fragment softmax (rows rb+lg, rb+lg+8) ----
#pragma unroll
        for (int r = 0; r < 2; ++r) {
            int row = rb + lg + 8 * r;
            unsigned mwA = Ms[row * 2], mwB = Ms[row * 2 + 1];
            int t0 = 2 * r;            // sc[nj][t0], sc[nj][t0+1] = this row
            float rm = -1e30f;
#pragma unroll
            for (int nj = 0; nj < 8; ++nj) {
                int col = 8 * nj + 2 * lk;
                unsigned word = (nj < 4) ? mwA : mwB;
                float v0 = ((word >> (col & 31)) & 1u) ? sc[nj][t0] * 0.125f : NEGVAL;
                float v1 = ((word >> ((col + 1) & 31)) & 1u) ? sc[nj][t0 + 1] * 0.125f : NEGVAL;
                sc[nj][t0] = v0;
                sc[nj][t0 + 1] = v1;
                rm = fmaxf(rm, fmaxf(v0, v1));
            }
            rm = fmaxf(rm, __shfl_xor_sync(0xffffffffu, rm, 1));
            rm = fmaxf(rm, __shfl_xor_sync(0xffffffffu, rm, 2));
            float mn = fmaxf(m_run[r], rm);
            float corr = __expf(m_run[r] - mn);
            m_run[r] = mn;
            float ls = 0.f;
#pragma unroll
            for (int nj = 0; nj < 8; ++nj) {
                float p0 = __uint_as_float(f2tf32(__expf(sc[nj][t0] - mn)));
                float p1 = __uint_as_float(f2tf32(__expf(sc[nj][t0 + 1] - mn)));
                sc[nj][t0] = p0;
                sc[nj][t0 + 1] = p1;
                ls += p0 + p1;
            }
            ls += __shfl_xor_sync(0xffffffffu, ls, 1);
            ls += __shfl_xor_sync(0xffffffffu, ls, 2);
            l_run[r] = l_run[r] * corr + ls;
#pragma unroll
            for (int nj = 0; nj < 8; ++nj) {
                o[nj][t0] *= corr;
                o[nj][t0 + 1] *= corr;
            }
            // stage P rows (warp-private) for the PV A-operand
#pragma unroll
            for (int nj = 0; nj < 8; ++nj)
                *(float2*)&Ps[row * QPAD + 8 * nj + 2 * lk] =
                    make_float2(sc[nj][t0], sc[nj][t0 + 1]);
        }
        __syncwarp();

        // ---- O += P @ V (mma) ----
#pragma unroll
        for (int ks = 0; ks < 8; ++ks) {
            uint32_t af[4];
            af[0] = __float_as_uint(Ps[(rb + lg) * QPAD + ks * 8 + lk]);
            af[1] = __float_as_uint(Ps[(rb + lg + 8) * QPAD + ks * 8 + lk]);
            af[2] = __float_as_uint(Ps[(rb + lg) * QPAD + ks * 8 + lk + 4]);
            af[3] = __float_as_uint(Ps[(rb + lg + 8) * QPAD + ks * 8 + lk + 4]);
#pragma unroll
            for (int nj = 0; nj < 8; ++nj) {
                int nb = 8 * nj + lg;
                uint32_t b0 = Vs[(ks * 8 + lk) * KPAD + nb];
                uint32_t b1 = Vs[(ks * 8 + lk + 4) * KPAD + nb];
                mma_tf32(o[nj], af, b0, b1);
            }
        }
    }

    // ---- normalize and write context (B,N,D) ----
    float inv0 = 1.0f / l_run[0], inv1 = 1.0f / l_run[1];
    float* Cg = g_C + ((size_t)(b * NSEQ + q0)) * DMODEL + h * DKH;
#pragma unroll
    for (int nj = 0; nj < 8; ++nj) {
        int col = 8 * nj + 2 * lk;
        *(float2*)&Cg[(size_t)(rb + lg) * DMODEL + col] =
            make_float2(o[nj][0] * inv0, o[nj][1] * inv0);
        *(float2*)&Cg[(size_t)(rb + lg + 8) * DMODEL + col] =
            make_float2(o[nj][2] * inv1, o[nj][3] * inv1);
    }
}

// ---------------- launch ----------------------------------------------------
extern "C" void kernel_launch(void* const* d_in, const int* in_sizes, int n_in,
                              void* d_out, int out_size) {
    const float* query = (const float*)d_in[0];
    const float* key   = (const float*)d_in[1];
    const float* value = (const float*)d_in[2];
    const int*   mask  = (const int*)d_in[3];
    const float* Wq = (const float*)d_in[4];
    const float* bq = (const float*)d_in[5];
    const float* Wk = (const float*)d_in[6];
    const float* bk = (const float*)d_in[7];
    const float* Wv = (const float*)d_in[8];
    const float* bv = (const float*)d_in[9];
    const float* Wo = (const float*)d_in[10];
    const float* bo = (const float*)d_in[11];
    float* out = (float*)d_out;

    float *pQ, *pK, *pV, *pC;
    cudaGetSymbolAddress((void**)&pQ, g_Q);
    cudaGetSymbolAddress((void**)&pK, g_K);
    cudaGetSymbolAddress((void**)&pV, g_V);
    cudaGetSymbolAddress((void**)&pC, g_C);

    // 1) pack mask to bits
    pack_mask_kernel<<<(BATCH * NSEQ * NSEQ) / 256, 256>>>(mask);

    // 2) Q/K/V projections (2xTF32, cp.async pipelined), one merged launch
    dim3 gq(DMODEL / 128, MROWS / 128, 3);
    proj_qkv_kernel<<<gq, 256>>>(query, key, value, Wq, Wk, Wv,
                                 bq, bk, bv, pQ, pK, pV);

    // 3) fused masked attention (tf32 mma, fragment softmax)
    const int attn_smem = 128 * QPAD * 4 + 2 * 64 * KPAD * 4 + 128 * 2 * 4; // 72704
    cudaFuncSetAttribute(attn_kernel, cudaFuncAttributeMaxDynamicSharedMemorySize,
                         attn_smem);
    attn_kernel<<<dim3(NSEQ / 128, BATCH * NHEAD), 256, attn_smem>>>();

    // 4) output projection (2xTF32, cp.async pipelined) -> d_out
    dim3 go(DMODEL / 128, MROWS / 128);
    proj_out_kernel<<<go, 256>>>(pC, Wo, bo, out);
}